// round 3
// baseline (speedup 1.0000x reference)
#include <cuda_runtime.h>

#define NB    32768
#define QK    4096
#define NBLK1 1024
#define XSTR  20

__device__ float g_M[256];
__device__ float g_pm[(size_t)NBLK1 * QK];
__device__ float g_ps[(size_t)NBLK1 * QK];
__device__ float g_moff[QK];
__device__ float g_u[(size_t)NB * 1024];

// -------- k0: M = Wq @ Wk^T / 3
__global__ void k0_prep(const float* __restrict__ Wq, const float* __restrict__ Wk) {
    int t = threadIdx.x, i = t >> 4, j = t & 15;
    float a = 0.f;
#pragma unroll
    for (int o = 0; o < 16; ++o) a += Wq[i * 16 + o] * Wk[j * 16 + o];
    g_M[t] = a * (1.0f / 3.0f);
}

__device__ __forceinline__ void stage_x(float* xs, const float* __restrict__ xb, int tid) {
    // 256 threads x float4 -> 64 rows x 16 cols, padded stride XSTR
    int r = tid >> 2, c4 = (tid & 3) << 2;
    *reinterpret_cast<float4*>(&xs[r * XSTR + c4]) =
        *reinterpret_cast<const float4*>(&xb[r * 16 + c4]);
}

__device__ __forceinline__ void score_tile(const float* ts, const float* xs,
                                           int ty, int tx, float acc[16]) {
#pragma unroll
    for (int j = 0; j < 16; ++j) acc[j] = 0.f;
#pragma unroll
    for (int d4 = 0; d4 < 4; ++d4) {
        float4 a[4], bb[4];
#pragma unroll
        for (int r = 0; r < 4; ++r)
            a[r] = *reinterpret_cast<const float4*>(&ts[(ty + 16 * r) * XSTR + d4 * 4]);
#pragma unroll
        for (int c = 0; c < 4; ++c)
            bb[c] = *reinterpret_cast<const float4*>(&xs[(tx + 16 * c) * XSTR + d4 * 4]);
#pragma unroll
        for (int r = 0; r < 4; ++r)
#pragma unroll
            for (int c = 0; c < 4; ++c) {
                float s = acc[r * 4 + c];
                s = fmaf(a[r].x, bb[c].x, s);
                s = fmaf(a[r].y, bb[c].y, s);
                s = fmaf(a[r].z, bb[c].z, s);
                s = fmaf(a[r].w, bb[c].w, s);
                acc[r * 4 + c] = s;
            }
    }
}

// -------- k1: per-block online softmax partials over batch axis
__global__ __launch_bounds__(256) void k1_maxsum(const float* __restrict__ x) {
    __shared__ __align__(16) float xs[64 * XSTR];
    __shared__ __align__(16) float ts[64 * XSTR];
    __shared__ __align__(16) float Ms[256];
    const int tid = threadIdx.x;
    Ms[tid] = g_M[tid];
    const int ty = tid >> 4, tx = tid & 15;
    const int tq = tid >> 2, tob = (tid & 3) << 2;

    float rm[16], rs[16];
#pragma unroll
    for (int j = 0; j < 16; ++j) { rm[j] = -1e30f; rs[j] = 0.f; }

    for (int b = blockIdx.x; b < NB; b += NBLK1) {
        __syncthreads();
        stage_x(xs, x + (size_t)b * 1024, tid);
        __syncthreads();
        {   // t = x @ M
            float4 ta = make_float4(0.f, 0.f, 0.f, 0.f);
#pragma unroll
            for (int d = 0; d < 16; ++d) {
                float xv = xs[tq * XSTR + d];
                float4 mm = *reinterpret_cast<const float4*>(&Ms[d * 16 + tob]);
                ta.x = fmaf(xv, mm.x, ta.x); ta.y = fmaf(xv, mm.y, ta.y);
                ta.z = fmaf(xv, mm.z, ta.z); ta.w = fmaf(xv, mm.w, ta.w);
            }
            *reinterpret_cast<float4*>(&ts[tq * XSTR + tob]) = ta;
        }
        __syncthreads();
        float acc[16];
        score_tile(ts, xs, ty, tx, acc);
#pragma unroll
        for (int j = 0; j < 16; ++j) {
            float v = acc[j];
            if (v > rm[j]) { rs[j] = fmaf(rs[j], __expf(rm[j] - v), 1.f); rm[j] = v; }
            else { float dd = v - rm[j]; if (dd > -80.f) rs[j] += __expf(dd); }
        }
    }
#pragma unroll
    for (int j = 0; j < 16; ++j) {
        int q = ty + 16 * (j >> 2), k = tx + 16 * (j & 3);
        g_pm[(size_t)blockIdx.x * QK + q * 64 + k] = rm[j];
        g_ps[(size_t)blockIdx.x * QK + q * 64 + k] = rs[j];
    }
}

// -------- k2: combine partials -> moff = m + ln(S)
__global__ void k2_reduce() {
    int pos = blockIdx.x * 256 + threadIdx.x;
    float m = -1e30f;
    for (int p = 0; p < NBLK1; ++p) m = fmaxf(m, g_pm[(size_t)p * QK + pos]);
    float S = 0.f;
    for (int p = 0; p < NBLK1; ++p)
        S += g_ps[(size_t)p * QK + pos] * __expf(g_pm[(size_t)p * QK + pos] - m);
    g_moff[pos] = m + __logf(S);
}

// -------- k3: attention + residual + joint LN -> g_u
__global__ __launch_bounds__(256) void k3_attn(const float* __restrict__ x,
                                               const float* __restrict__ Wv) {
    __shared__ __align__(16) float xs[64 * XSTR];
    __shared__ __align__(16) float ts[64 * XSTR];
    __shared__ __align__(16) float vs[64 * XSTR];
    __shared__ float es[64 * 65];
    __shared__ __align__(16) float Ms[256];
    __shared__ __align__(16) float Wvs[256];
    __shared__ float rbuf[18];
    const int tid = threadIdx.x;
    Ms[tid] = g_M[tid];
    Wvs[tid] = Wv[tid];
    const int ty = tid >> 4, tx = tid & 15;
    const int tq = tid >> 2, tob = (tid & 3) << 2;
    const int lane = tid & 31, wid = tid >> 5;

    float rmoff[16];
#pragma unroll
    for (int j = 0; j < 16; ++j)
        rmoff[j] = g_moff[(ty + 16 * (j >> 2)) * 64 + tx + 16 * (j & 3)];

    for (int b = blockIdx.x; b < NB; b += gridDim.x) {
        __syncthreads();
        stage_x(xs, x + (size_t)b * 1024, tid);
        __syncthreads();
        {   // t = x @ M ; V = x @ Wv
            float4 ta = make_float4(0.f, 0.f, 0.f, 0.f);
            float4 va = make_float4(0.f, 0.f, 0.f, 0.f);
#pragma unroll
            for (int d = 0; d < 16; ++d) {
                float xv = xs[tq * XSTR + d];
                float4 mm = *reinterpret_cast<const float4*>(&Ms[d * 16 + tob]);
                float4 wv = *reinterpret_cast<const float4*>(&Wvs[d * 16 + tob]);
                ta.x = fmaf(xv, mm.x, ta.x); ta.y = fmaf(xv, mm.y, ta.y);
                ta.z = fmaf(xv, mm.z, ta.z); ta.w = fmaf(xv, mm.w, ta.w);
                va.x = fmaf(xv, wv.x, va.x); va.y = fmaf(xv, wv.y, va.y);
                va.z = fmaf(xv, wv.z, va.z); va.w = fmaf(xv, wv.w, va.w);
            }
            *reinterpret_cast<float4*>(&ts[tq * XSTR + tob]) = ta;
            *reinterpret_cast<float4*>(&vs[tq * XSTR + tob]) = va;
        }
        __syncthreads();
        {
            float acc[16];
            score_tile(ts, xs, ty, tx, acc);
#pragma unroll
            for (int j = 0; j < 16; ++j)
                es[(ty + 16 * (j >> 2)) * 65 + tx + 16 * (j & 3)] = __expf(acc[j] - rmoff[j]);
        }
        __syncthreads();
        // z = e @ V ; u = x + z ; LN over 1024
        float4 z = make_float4(0.f, 0.f, 0.f, 0.f);
#pragma unroll 4
        for (int k = 0; k < 64; ++k) {
            float e = es[tq * 65 + k];
            float4 v = *reinterpret_cast<const float4*>(&vs[k * XSTR + tob]);
            z.x = fmaf(e, v.x, z.x); z.y = fmaf(e, v.y, z.y);
            z.z = fmaf(e, v.z, z.z); z.w = fmaf(e, v.w, z.w);
        }
        float4 xv4 = *reinterpret_cast<const float4*>(&xs[tq * XSTR + tob]);
        float4 u = make_float4(xv4.x + z.x, xv4.y + z.y, xv4.z + z.z, xv4.w + z.w);

        float ps = u.x + u.y + u.z + u.w;
        float pss = fmaf(u.x, u.x, fmaf(u.y, u.y, fmaf(u.z, u.z, u.w * u.w)));
#pragma unroll
        for (int o = 16; o > 0; o >>= 1) {
            ps  += __shfl_down_sync(0xffffffffu, ps, o);
            pss += __shfl_down_sync(0xffffffffu, pss, o);
        }
        if (lane == 0) { rbuf[wid] = ps; rbuf[8 + wid] = pss; }
        __syncthreads();
        if (tid == 0) {
            float s = 0.f, ss = 0.f;
#pragma unroll
            for (int w = 0; w < 8; ++w) { s += rbuf[w]; ss += rbuf[8 + w]; }
            float mean = s * (1.f / 1024.f);
            float var = ss * (1.f / 1024.f) - mean * mean;
            rbuf[16] = mean; rbuf[17] = rsqrtf(var + 1e-5f);
        }
        __syncthreads();
        float mean = rbuf[16], rstd = rbuf[17];
        float4 o = make_float4((u.x - mean) * rstd, (u.y - mean) * rstd,
                               (u.z - mean) * rstd, (u.w - mean) * rstd);
        *reinterpret_cast<float4*>(g_u + (size_t)b * 1024 + tid * 4) = o;
    }
}

// -------- k4: 64 per-patch MLPs + residual + LN -> out
__global__ __launch_bounds__(256, 1) void k4_mlp(const float* __restrict__ W1,
                                                 const float* __restrict__ b1,
                                                 const float* __restrict__ W2,
                                                 const float* __restrict__ b2,
                                                 float* __restrict__ out) {
    const int tid = threadIdx.x;
    const int p = tid >> 2, ob = (tid & 3) << 2;
    const int lane = tid & 31, wid = tid >> 5;
    float4 rw1[16], rw2[16];
#pragma unroll
    for (int i = 0; i < 16; ++i) {
        rw1[i] = *reinterpret_cast<const float4*>(&W1[p * 256 + i * 16 + ob]);
        rw2[i] = *reinterpret_cast<const float4*>(&W2[p * 256 + i * 16 + ob]);
    }
    float4 rb1 = *reinterpret_cast<const float4*>(&b1[p * 16 + ob]);
    float4 rb2 = *reinterpret_cast<const float4*>(&b2[p * 16 + ob]);

    __shared__ __align__(16) float xs[64 * XSTR];
    __shared__ float hs[64 * XSTR];
    __shared__ float rbuf[18];

    for (int b = blockIdx.x; b < NB; b += gridDim.x) {
        __syncthreads();
        stage_x(xs, g_u + (size_t)b * 1024, tid);
        __syncthreads();
        float4 h = rb1;
#pragma unroll
        for (int i = 0; i < 16; ++i) {
            float xv = xs[p * XSTR + i];
            h.x = fmaf(xv, rw1[i].x, h.x); h.y = fmaf(xv, rw1[i].y, h.y);
            h.z = fmaf(xv, rw1[i].z, h.z); h.w = fmaf(xv, rw1[i].w, h.w);
        }
        h.x = fmaxf(h.x, 0.f); h.y = fmaxf(h.y, 0.f);
        h.z = fmaxf(h.z, 0.f); h.w = fmaxf(h.w, 0.f);
        hs[p * XSTR + ob] = h.x; hs[p * XSTR + ob + 1] = h.y;
        hs[p * XSTR + ob + 2] = h.z; hs[p * XSTR + ob + 3] = h.w;
        __syncthreads();
        float4 h2 = rb2;
#pragma unroll
        for (int i = 0; i < 16; ++i) {
            float hv = hs[p * XSTR + i];
            h2.x = fmaf(hv, rw2[i].x, h2.x); h2.y = fmaf(hv, rw2[i].y, h2.y);
            h2.z = fmaf(hv, rw2[i].z, h2.z); h2.w = fmaf(hv, rw2[i].w, h2.w);
        }
        float4 u;
        u.x = fmaxf(h2.x, 0.f) + xs[p * XSTR + ob];
        u.y = fmaxf(h2.y, 0.f) + xs[p * XSTR + ob + 1];
        u.z = fmaxf(h2.z, 0.f) + xs[p * XSTR + ob + 2];
        u.w = fmaxf(h2.w, 0.f) + xs[p * XSTR + ob + 3];

        float ps = u.x + u.y + u.z + u.w;
        float pss = fmaf(u.x, u.x, fmaf(u.y, u.y, fmaf(u.z, u.z, u.w * u.w)));
#pragma unroll
        for (int o = 16; o > 0; o >>= 1) {
            ps  += __shfl_down_sync(0xffffffffu, ps, o);
            pss += __shfl_down_sync(0xffffffffu, pss, o);
        }
        if (lane == 0) { rbuf[wid] = ps; rbuf[8 + wid] = pss; }
        __syncthreads();
        if (tid == 0) {
            float s = 0.f, ss = 0.f;
#pragma unroll
            for (int w = 0; w < 8; ++w) { s += rbuf[w]; ss += rbuf[8 + w]; }
            float mean = s * (1.f / 1024.f);
            float var = ss * (1.f / 1024.f) - mean * mean;
            rbuf[16] = mean; rbuf[17] = rsqrtf(var + 1e-5f);
        }
        __syncthreads();
        float mean = rbuf[16], rstd = rbuf[17];
        float4 o = make_float4((u.x - mean) * rstd, (u.y - mean) * rstd,
                               (u.z - mean) * rstd, (u.w - mean) * rstd);
        *reinterpret_cast<float4*>(out + (size_t)b * 1024 + tid * 4) = o;
    }
}

extern "C" void kernel_launch(void* const* d_in, const int* in_sizes, int n_in,
                              void* d_out, int out_size) {
    const float* x  = (const float*)d_in[0];
    const float* Wq = (const float*)d_in[1];
    const float* Wk = (const float*)d_in[2];
    const float* Wv = (const float*)d_in[3];
    const float* W1 = (const float*)d_in[4];
    const float* b1 = (const float*)d_in[5];
    const float* W2 = (const float*)d_in[6];
    const float* b2 = (const float*)d_in[7];
    float* out = (float*)d_out;

    k0_prep<<<1, 256>>>(Wq, Wk);
    k1_maxsum<<<NBLK1, 256>>>(x);
    k2_reduce<<<QK / 256, 256>>>();
    k3_attn<<<2048, 256>>>(x, Wv);
    k4_mlp<<<2048, 256>>>(W1, b1, W2, b2, out);
}